// round 1
// baseline (speedup 1.0000x reference)
#include <cuda_runtime.h>
#include <cuda_bf16.h>

#define FULL 0xFFFFFFFFu

constexpr int BATCH = 4096;
constexpr int DIM = 32;
constexpr int N_MEM = 32;
constexpr int N_HOP = 2;

__global__ void __launch_bounds__(256) ripple_kernel(
    const int* __restrict__ items,
    const int* __restrict__ mem_h,
    const int* __restrict__ mem_r,
    const int* __restrict__ mem_t,
    const int* __restrict__ users,
    const float* __restrict__ entity,
    const float* __restrict__ relation,
    const float* __restrict__ user_table,
    const float* __restrict__ W,
    float* __restrict__ out)
{
    __shared__ float Wt[DIM * DIM];  // W transposed: Wt[e*32+d] = W[d*32+e]

    const int tid = threadIdx.x;
    // Stage transposed transform matrix once per block (4 KB, trivial).
    for (int i = tid; i < DIM * DIM; i += blockDim.x) {
        int d = i >> 5, e = i & 31;
        Wt[e * DIM + d] = W[i];
    }
    __syncthreads();

    const int lane = tid & 31;
    const int warp = tid >> 5;
    const int b = blockIdx.x * (blockDim.x >> 5) + warp;  // exact grid: always < BATCH

    // item[lane] — one dim per lane
    float item = entity[items[b] * DIM + lane];
    float y = 0.f;

    #pragma unroll
    for (int hop = 0; hop < N_HOP; ++hop) {
        const int base = hop * BATCH * N_MEM + b * N_MEM;
        // lane m holds the indices for memory m (coalesced loads)
        const int hidx = mem_h[base + lane];
        const int ridx = mem_r[base + lane];
        const int tidx = mem_t[base + lane];

        float mylogit = 0.f;  // lane m will own logit[m]

        // ---- logits: logit[m] = item^T R_{r_m} h_m computed as (item^T R) . h ----
        // float2 layout: lanes 0-15 cover row pairs starting at even d, lanes 16-31 odd d.
        const int rowoff = lane >> 4;   // 0 or 1
        const int colp   = lane & 15;   // float2 column index (e = 2*colp, 2*colp+1)

        for (int m = 0; m < N_MEM; ++m) {
            const int h_i = __shfl_sync(FULL, hidx, m);
            const int r_i = __shfl_sync(FULL, ridx, m);
            const float2* __restrict__ R2 = (const float2*)(relation + r_i * (DIM * DIM));

            float accx = 0.f, accy = 0.f;
            #pragma unroll
            for (int k = 0; k < 16; ++k) {
                const int d = 2 * k + rowoff;
                float2 r2 = R2[d * 16 + colp];       // coalesced: 2 lines / instr
                float it = __shfl_sync(FULL, item, d);
                accx = fmaf(it, r2.x, accx);
                accy = fmaf(it, r2.y, accy);
            }
            // partial v (split over d-parity across lane halves) dotted with h;
            // full warp reduce sums both the e-dimension and the d-parity split.
            const float2* __restrict__ H2 = (const float2*)(entity + h_i * DIM);
            float2 h2 = H2[colp];                    // broadcast within halves, 1 line
            float s = accx * h2.x + accy * h2.y;
            #pragma unroll
            for (int off = 16; off; off >>= 1)
                s += __shfl_xor_sync(FULL, s, off);
            if (lane == m) mylogit = s;
        }

        // ---- softmax over the 32 memories (lane m owns memory m) ----
        float mx = mylogit;
        #pragma unroll
        for (int off = 16; off; off >>= 1)
            mx = fmaxf(mx, __shfl_xor_sync(FULL, mx, off));
        float ex = __expf(mylogit - mx);
        float denom = ex;
        #pragma unroll
        for (int off = 16; off; off >>= 1)
            denom += __shfl_xor_sync(FULL, denom, off);
        const float prob = ex / denom;

        // ---- o[d] = sum_m prob[m] * t_m[d] (lane = d) ----
        float o = 0.f;
        for (int m = 0; m < N_MEM; ++m) {
            const int t_i = __shfl_sync(FULL, tidx, m);
            const float p = __shfl_sync(FULL, prob, m);
            o = fmaf(p, entity[t_i * DIM + lane], o);
        }
        y += o;

        // ---- item = (item + o) @ W^T  via transposed-W smem matvec ----
        const float tmp = item + o;
        float acc = 0.f;
        #pragma unroll
        for (int e = 0; e < DIM; ++e)
            acc = fmaf(__shfl_sync(FULL, tmp, e), Wt[e * DIM + lane], acc);
        item = acc;
    }

    // ---- score = sigmoid(item . (o0 + o1 + user_emb)) ----
    y += user_table[users[b] * DIM + lane];
    float s = item * y;
    #pragma unroll
    for (int off = 16; off; off >>= 1)
        s += __shfl_xor_sync(FULL, s, off);
    if (lane == 0)
        out[b] = 1.f / (1.f + __expf(-s));
}

extern "C" void kernel_launch(void* const* d_in, const int* in_sizes, int n_in,
                              void* d_out, int out_size) {
    const int*   items     = (const int*)d_in[0];
    // d_in[1] = labels (unused)
    const int*   mem_h     = (const int*)d_in[2];
    const int*   mem_r     = (const int*)d_in[3];
    const int*   mem_t     = (const int*)d_in[4];
    const int*   users     = (const int*)d_in[5];
    const float* entity    = (const float*)d_in[6];
    const float* relation  = (const float*)d_in[7];
    const float* user_tab  = (const float*)d_in[8];
    const float* W         = (const float*)d_in[9];
    float* out = (float*)d_out;

    // 4096 batch elements, 1 warp each, 8 warps per block -> 512 blocks
    ripple_kernel<<<BATCH / 8, 256>>>(items, mem_h, mem_r, mem_t, users,
                                      entity, relation, user_tab, W, out);
}

// round 2
// speedup vs baseline: 1.4956x; 1.4956x over previous
#include <cuda_runtime.h>
#include <cuda_bf16.h>

#define FULL 0xFFFFFFFFu

constexpr int BATCH = 4096;
constexpr int DIM   = 32;
constexpr int N_MEM = 32;
constexpr int N_HOP = 2;
constexpr int WPB   = 8;    // warps per block
constexpr int PSTR  = 33;   // padded row stride for partial matrix

__global__ void __launch_bounds__(256) ripple_kernel(
    const int* __restrict__ items,
    const int* __restrict__ mem_h,
    const int* __restrict__ mem_r,
    const int* __restrict__ mem_t,
    const int* __restrict__ users,
    const float* __restrict__ entity,
    const float* __restrict__ relation,
    const float* __restrict__ user_table,
    const float* __restrict__ W,
    float* __restrict__ out)
{
    __shared__ float Wt[DIM * DIM];              // W transposed
    __shared__ float P[WPB][N_MEM * PSTR];       // per-warp partial matrix

    const int tid = threadIdx.x;
    for (int i = tid; i < DIM * DIM; i += blockDim.x) {
        int d = i >> 5, e = i & 31;
        Wt[e * DIM + d] = W[i];
    }
    __syncthreads();

    const int lane = tid & 31;
    const int warp = tid >> 5;
    const int b = blockIdx.x * WPB + warp;

    const int g = lane >> 3;   // row-group 0..3 (d = 4k + g)
    const int c = lane & 7;    // float4 col-group 0..7 (e = 4c .. 4c+3)

    float* __restrict__ Pw = P[warp];

    // item[lane] — one dim per lane
    float item = entity[items[b] * DIM + lane];
    float y = 0.f;

    #pragma unroll
    for (int hop = 0; hop < N_HOP; ++hop) {
        const int base = hop * BATCH * N_MEM + b * N_MEM;
        const int hidx = mem_h[base + lane];   // lane m holds memory m's indices
        const int ridx = mem_r[base + lane];
        const int tidx = mem_t[base + lane];

        __syncwarp();   // P reuse across hops: prior reads done before new stores

        // ---- partials: each lane covers d ∈ {g,4+g,..}, e ∈ {4c..4c+3} ----
        #pragma unroll 4
        for (int m = 0; m < N_MEM; ++m) {
            const int r_i = __shfl_sync(FULL, ridx, m);
            const int h_i = __shfl_sync(FULL, hidx, m);
            const float4* __restrict__ R4 =
                (const float4*)(relation + r_i * (DIM * DIM));

            float4 acc = make_float4(0.f, 0.f, 0.f, 0.f);
            #pragma unroll
            for (int k = 0; k < 8; ++k) {
                const int d = 4 * k + g;
                const float4 r4 = R4[d * 8 + c];           // 1 line per 8 lanes
                const float it = __shfl_sync(FULL, item, d);
                acc.x = fmaf(it, r4.x, acc.x);
                acc.y = fmaf(it, r4.y, acc.y);
                acc.z = fmaf(it, r4.z, acc.z);
                acc.w = fmaf(it, r4.w, acc.w);
            }
            const float4 h4 = ((const float4*)(entity + h_i * DIM))[c];
            Pw[m * PSTR + lane] =
                acc.x * h4.x + acc.y * h4.y + acc.z * h4.z + acc.w * h4.w;
        }
        __syncwarp();

        // ---- logit[m] = row-sum of P[m][*] (lane m owns memory m) ----
        float logit = 0.f;
        {
            const float* __restrict__ row = &Pw[lane * PSTR];
            #pragma unroll
            for (int j = 0; j < 32; ++j) logit += row[j];
        }

        // ---- softmax over 32 memories ----
        float mx = logit;
        #pragma unroll
        for (int off = 16; off; off >>= 1)
            mx = fmaxf(mx, __shfl_xor_sync(FULL, mx, off));
        const float ex = __expf(logit - mx);
        float denom = ex;
        #pragma unroll
        for (int off = 16; off; off >>= 1)
            denom += __shfl_xor_sync(FULL, denom, off);
        const float prob = ex / denom;

        // ---- o[d] = sum_m prob[m] * t_m[d]  (lane = d) ----
        float o = 0.f;
        #pragma unroll 4
        for (int m = 0; m < N_MEM; ++m) {
            const int t_i = __shfl_sync(FULL, tidx, m);
            const float p = __shfl_sync(FULL, prob, m);
            o = fmaf(p, entity[t_i * DIM + lane], o);
        }
        y += o;

        // ---- item = (item + o) @ W^T via transposed-W smem ----
        const float tmp = item + o;
        float accw = 0.f;
        #pragma unroll
        for (int e = 0; e < DIM; ++e)
            accw = fmaf(__shfl_sync(FULL, tmp, e), Wt[e * DIM + lane], accw);
        item = accw;
    }

    // ---- score = sigmoid(item . (o0 + o1 + user_emb)) ----
    y += user_table[users[b] * DIM + lane];
    float s = item * y;
    #pragma unroll
    for (int off = 16; off; off >>= 1)
        s += __shfl_xor_sync(FULL, s, off);
    if (lane == 0)
        out[b] = 1.f / (1.f + __expf(-s));
}

extern "C" void kernel_launch(void* const* d_in, const int* in_sizes, int n_in,
                              void* d_out, int out_size) {
    const int*   items     = (const int*)d_in[0];
    const int*   mem_h     = (const int*)d_in[2];
    const int*   mem_r     = (const int*)d_in[3];
    const int*   mem_t     = (const int*)d_in[4];
    const int*   users     = (const int*)d_in[5];
    const float* entity    = (const float*)d_in[6];
    const float* relation  = (const float*)d_in[7];
    const float* user_tab  = (const float*)d_in[8];
    const float* W         = (const float*)d_in[9];
    float* out = (float*)d_out;

    ripple_kernel<<<BATCH / WPB, 256>>>(items, mem_h, mem_r, mem_t, users,
                                        entity, relation, user_tab, W, out);
}